// round 1
// baseline (speedup 1.0000x reference)
#include <cuda_runtime.h>

// Depthwise 3x3 conv (IN_CH=256, 2 filters/ch -> 512 intermediate) fused with
// butterfly wing-swap add. For output channel c (0..255):
//   out[c] = conv(x[c], w[2c]) + conv(x[c'], w[2c'+1]),
//   c' = (c & ~7) | ((c+4) & 7)   (involution: partner(c') == c)
// One block computes BOTH out[c] and out[c'] from the two shared input tiles.

#define BN 32
#define CH 256
#define HH 56
#define WW 56
#define TH 8          // output rows per block
#define SW 64         // smem row stride (power of 2, conflict-free)
#define NTHREADS 256

__global__ __launch_bounds__(NTHREADS)
void conv_butterfly_kernel(const float* __restrict__ x,
                           const float* __restrict__ w,
                           float* __restrict__ out)
{
    const int tile = blockIdx.x;      // 0..6  (7 * 8 = 56 rows)
    const int p    = blockIdx.y;      // 0..127 channel pair
    const int n    = blockIdx.z;      // 0..31 batch

    // pair p -> (c, c+4) within butterfly (p>>2), wing slot (p&3)
    const int c  = ((p >> 2) << 3) + (p & 3);
    const int cp = c + 4;
    const int h0 = tile * TH;

    __shared__ float s0[(TH + 2) * SW];   // tile of x[n, c]
    __shared__ float s1[(TH + 2) * SW];   // tile of x[n, cp]

    const size_t plane = (size_t)HH * WW;
    const float* x0 = x + ((size_t)n * CH + c)  * plane;
    const float* x1 = x + ((size_t)n * CH + cp) * plane;

    const int tid = threadIdx.x;

    // Load (TH+2) x 58 halo tile for both channels, zero-padded.
    for (int i = tid; i < (TH + 2) * 58; i += NTHREADS) {
        const int r   = i / 58;
        const int col = i % 58;
        const int h   = h0 - 1 + r;
        const int wp  = col - 1;
        float v0 = 0.f, v1 = 0.f;
        if (h >= 0 && h < HH && wp >= 0 && wp < WW) {
            v0 = __ldg(x0 + h * WW + wp);
            v1 = __ldg(x1 + h * WW + wp);
        }
        s0[r * SW + col] = v0;
        s1[r * SW + col] = v1;
    }

    // Weight sets:
    //   out[c]  = conv(x[c], w[2c])   + conv(x[cp], w[2cp+1])
    //   out[cp] = conv(x[cp], w[2cp]) + conv(x[c],  w[2c+1])
    float wa[9], wb[9], wc9[9], wd[9];
    const float* wbase_a = w + (size_t)(2 * c)      * 9;
    const float* wbase_b = w + (size_t)(2 * cp + 1) * 9;
    const float* wbase_c = w + (size_t)(2 * cp)     * 9;
    const float* wbase_d = w + (size_t)(2 * c + 1)  * 9;
    #pragma unroll
    for (int i = 0; i < 9; i++) {
        wa[i]  = __ldg(wbase_a + i);
        wb[i]  = __ldg(wbase_b + i);
        wc9[i] = __ldg(wbase_c + i);
        wd[i]  = __ldg(wbase_d + i);
    }

    __syncthreads();

    float* o0 = out + ((size_t)n * CH + c)  * plane + (size_t)h0 * WW;
    float* o1 = out + ((size_t)n * CH + cp) * plane + (size_t)h0 * WW;

    for (int i = tid; i < TH * WW; i += NTHREADS) {
        const int r   = i / WW;
        const int col = i % WW;
        float acc0 = 0.f, acc1 = 0.f;
        #pragma unroll
        for (int dr = 0; dr < 3; dr++) {
            #pragma unroll
            for (int dc = 0; dc < 3; dc++) {
                const float v0 = s0[(r + dr) * SW + (col + dc)];
                const float v1 = s1[(r + dr) * SW + (col + dc)];
                const float k  = (float)(dr * 3 + dc);
                acc0 = fmaf(v0, wa[dr * 3 + dc], acc0);
                acc0 = fmaf(v1, wb[dr * 3 + dc], acc0);
                acc1 = fmaf(v1, wc9[dr * 3 + dc], acc1);
                acc1 = fmaf(v0, wd[dr * 3 + dc], acc1);
                (void)k;
            }
        }
        o0[i] = acc0;   // (h0+r)*WW + col == h0*WW + i : fully contiguous
        o1[i] = acc1;
    }
}

extern "C" void kernel_launch(void* const* d_in, const int* in_sizes, int n_in,
                              void* d_out, int out_size)
{
    const float* x = (const float*)d_in[0];
    const float* w = (const float*)d_in[1];
    float* out = (float*)d_out;
    (void)in_sizes; (void)n_in; (void)out_size;

    dim3 grid(HH / TH, CH / 2, BN);   // (7, 128, 32)
    conv_butterfly_kernel<<<grid, NTHREADS>>>(x, w, out);
}

// round 2
// speedup vs baseline: 2.0063x; 2.0063x over previous
#include <cuda_runtime.h>

// Depthwise 3x3 conv (256 ch x 2 filters) fused with butterfly wing-swap add.
//   out[c]  = conv(x[c],  w[2c])   + conv(x[cp], w[2cp+1])
//   out[cp] = conv(x[cp], w[2cp])  + conv(x[c],  w[2c+1]),   cp = c + 4 (within 8-ch butterfly)
// One block = one (batch, channel-pair), full 56x56 plane in smem (input read once chip-wide).
// Both output channels accumulated simultaneously via packed fma.rn.f32x2.

#define CH 256
#define HW 56
#define PLANE (HW * HW)      // 3136
#define ST 61                // smem row stride, odd -> conflict-free with 4-row x 8-col warp tile
#define SROWS 58
#define NTHREADS 256

typedef unsigned long long ull;

__device__ __forceinline__ ull fma2(ull a, ull b, ull c) {
    ull d; asm("fma.rn.f32x2 %0, %1, %2, %3;" : "=l"(d) : "l"(a), "l"(b), "l"(c)); return d;
}
__device__ __forceinline__ ull pack2(float lo, float hi) {
    ull r; asm("mov.b64 %0, {%1, %2};" : "=l"(r) : "f"(lo), "f"(hi)); return r;
}
__device__ __forceinline__ float2 unpack2(ull v) {
    float2 r; asm("mov.b64 {%0, %1}, %2;" : "=f"(r.x), "=f"(r.y) : "l"(v)); return r;
}

__global__ __launch_bounds__(NTHREADS, 2)
void conv_butterfly_kernel(const float* __restrict__ x,
                           const float* __restrict__ w,
                           float* __restrict__ out)
{
    __shared__ float s0[SROWS * ST];
    __shared__ float s1[SROWS * ST];

    const int p = blockIdx.x;            // 0..127 channel pair
    const int n = blockIdx.y;            // 0..31 batch
    const int c  = ((p >> 2) << 3) + (p & 3);
    const int cp = c + 4;
    const int tid = threadIdx.x;

    const float4* xv0 = (const float4*)(x + ((size_t)n * CH + c)  * PLANE);
    const float4* xv1 = (const float4*)(x + ((size_t)n * CH + cp) * PLANE);

    // ---- load both planes (56 rows x 14 float4 each), data cell (h,d) -> smem[(h+1)*ST + d+1]
    for (int i = tid; i < 2 * 784; i += NTHREADS) {
        const int chn = (i >= 784);
        const int ii  = chn ? i - 784 : i;
        const float4 v = chn ? xv1[ii] : xv0[ii];
        const int row = ii / 14;
        const int c4  = ii - row * 14;
        float* s = chn ? s1 : s0;
        const int off = (row + 1) * ST + c4 * 4 + 1;
        s[off + 0] = v.x; s[off + 1] = v.y; s[off + 2] = v.z; s[off + 3] = v.w;
    }
    // ---- zero halo pads (rows 0 & 57 full width 58; cols 0 & 57 of rows 1..56)
    for (int i = tid; i < 2 * 228; i += NTHREADS) {
        const int chn = (i >= 228);
        const int j = chn ? i - 228 : i;
        float* s = chn ? s1 : s0;
        int off;
        if (j < 58)        off = j;
        else if (j < 116)  off = 57 * ST + (j - 58);
        else { const int k = j - 116; off = (1 + (k >> 1)) * ST + (k & 1) * 57; }
        s[off] = 0.f;
    }

    // ---- packed weights: lo half -> out[c] accumulator, hi half -> out[cp]
    ull wp0[9], wp1[9];
    const float* wa = w + 18 * c;    // [w2c (9) | w2c+1 (9)]
    const float* wb = w + 18 * cp;   // [w2cp (9) | w2cp+1 (9)]
    #pragma unroll
    for (int k = 0; k < 9; k++) {
        wp0[k] = pack2(__ldg(wa + k),     __ldg(wa + 9 + k));  // src s0: (w2c, w2c+1)
        wp1[k] = pack2(__ldg(wb + 9 + k), __ldg(wb + k));      // src s1: (w2cp+1, w2cp)
    }

    __syncthreads();

    float* o0 = out + ((size_t)n * CH + c)  * PLANE;
    float* o1 = out + ((size_t)n * CH + cp) * PLANE;

    const int warpid = tid >> 5;
    const int lane   = tid & 31;
    const int lr = lane & 3;     // row within 4-row warp tile
    const int lc = lane >> 2;    // strip (vec4 column) within warp tile

    // item space: 14 row-tiles x 2 phases (strips 0..7, 8..13). 28 warp-items over 8 warps.
    for (int it = warpid; it < 28; it += 8) {
        const int c4 = ((it & 1) << 3) + lc;
        if (c4 >= 14) continue;                 // phase B: lanes with lc >= 6 idle
        const int r  = ((it >> 1) << 2) + lr;   // output row 0..55
        const int c0 = c4 << 2;                 // output col base (multiple of 4)

        ull pa0 = 0, pa1 = 0, pa2 = 0, pa3 = 0;

        #pragma unroll
        for (int dr = 0; dr < 3; dr++) {
            const float* q0 = s0 + (r + dr) * ST + c0;   // input row r-1+dr, cols c0-1..c0+4
            const float* q1 = s1 + (r + dr) * ST + c0;
            ull ad[6], bd[6];
            #pragma unroll
            for (int j = 0; j < 6; j++) { float v = q0[j]; ad[j] = pack2(v, v); }
            #pragma unroll
            for (int j = 0; j < 6; j++) { float v = q1[j]; bd[j] = pack2(v, v); }

            const ull w00 = wp0[dr*3+0], w01 = wp0[dr*3+1], w02 = wp0[dr*3+2];
            const ull w10 = wp1[dr*3+0], w11 = wp1[dr*3+1], w12 = wp1[dr*3+2];

            pa0 = fma2(ad[0], w00, pa0); pa0 = fma2(ad[1], w01, pa0); pa0 = fma2(ad[2], w02, pa0);
            pa1 = fma2(ad[1], w00, pa1); pa1 = fma2(ad[2], w01, pa1); pa1 = fma2(ad[3], w02, pa1);
            pa2 = fma2(ad[2], w00, pa2); pa2 = fma2(ad[3], w01, pa2); pa2 = fma2(ad[4], w02, pa2);
            pa3 = fma2(ad[3], w00, pa3); pa3 = fma2(ad[4], w01, pa3); pa3 = fma2(ad[5], w02, pa3);

            pa0 = fma2(bd[0], w10, pa0); pa0 = fma2(bd[1], w11, pa0); pa0 = fma2(bd[2], w12, pa0);
            pa1 = fma2(bd[1], w10, pa1); pa1 = fma2(bd[2], w11, pa1); pa1 = fma2(bd[3], w12, pa1);
            pa2 = fma2(bd[2], w10, pa2); pa2 = fma2(bd[3], w11, pa2); pa2 = fma2(bd[4], w12, pa2);
            pa3 = fma2(bd[3], w10, pa3); pa3 = fma2(bd[4], w11, pa3); pa3 = fma2(bd[5], w12, pa3);
        }

        const float2 u0 = unpack2(pa0), u1 = unpack2(pa1), u2 = unpack2(pa2), u3 = unpack2(pa3);
        float4 lo; lo.x = u0.x; lo.y = u1.x; lo.z = u2.x; lo.w = u3.x;
        float4 hi; hi.x = u0.y; hi.y = u1.y; hi.z = u2.y; hi.w = u3.y;
        *(float4*)(o0 + r * HW + c0) = lo;
        *(float4*)(o1 + r * HW + c0) = hi;
    }
}

extern "C" void kernel_launch(void* const* d_in, const int* in_sizes, int n_in,
                              void* d_out, int out_size)
{
    const float* x = (const float*)d_in[0];
    const float* w = (const float*)d_in[1];
    float* out = (float*)d_out;
    (void)in_sizes; (void)n_in; (void)out_size;

    dim3 grid(CH / 2, 32);   // (128 pairs, 32 batch)
    conv_butterfly_kernel<<<grid, NTHREADS>>>(x, w, out);
}